// round 7
// baseline (speedup 1.0000x reference)
#include <cuda_runtime.h>
#include <cuda_fp16.h>
#include <cuda_bf16.h>
#include <cstdint>

#define NN 100000
#define EE 1600000
#define EPAD (EE + 8 * NN)

// ---------------- scratch (static device globals; no allocation) ----------
__device__ int   g_is64;
__device__ int   g_cnt[NN];
__device__ int   g_rowoff[NN + 1];
__device__ int   g_cursor[NN];
__device__ float g_dinv[NN];
__device__ int   g_bsum[128];
__device__ int   g_boff[128];
__device__ __align__(16) long long g_ew[EPAD];               // packed (w<<32 | col)
__device__ __align__(16) __half    g_h16[(size_t)NN * 64];   // gemm out (fp16)
__device__ __align__(16) __half    g_a16[(size_t)NN * 64];   // agg out (fp16, gemm in)

// ---------------- small helpers ----------------------------------------
__device__ __forceinline__ void ffma2(unsigned long long& acc,
                                      unsigned long long a,
                                      unsigned long long b) {
    asm("fma.rn.f32x2 %0, %1, %2, %0;" : "+l"(acc) : "l"(a), "l"(b));
}
__device__ __forceinline__ unsigned long long pack_dup(float x) {
    unsigned long long r;
    asm("mov.b64 %0, {%1, %1};" : "=l"(r) : "f"(x));
    return r;
}
__device__ __forceinline__ float2 unpack2(unsigned long long v) {
    float2 f;
    asm("mov.b64 {%0, %1}, %2;" : "=f"(f.x), "=f"(f.y) : "l"(v));
    return f;
}

// ---------------- init: zero counters + dtype detection (block 0) -------
__global__ void k_init(const int* __restrict__ ei32, int n) {
    int i = blockIdx.x * blockDim.x + threadIdx.x;
    if (i < n) g_cnt[i] = 0;
    if (blockIdx.x == 0) {
        __shared__ int sor;
        if (threadIdx.x == 0) sor = 0;
        __syncthreads();
        int acc = 0;
        for (int k = threadIdx.x; k < 4096; k += blockDim.x)
            acc |= ei32[2 * k + 1];
        atomicOr(&sor, acc);
        __syncthreads();
        if (threadIdx.x == 0) g_is64 = (sor == 0) ? 1 : 0;
    }
}

__device__ __forceinline__ int edge_id(const void* ei, size_t idx) {
    if (g_is64) return (int)((const long long*)ei)[idx];
    return ((const int*)ei)[idx];
}

__global__ void k_count(const void* __restrict__ ei, int E) {
    int e = blockIdx.x * blockDim.x + threadIdx.x;
    if (e < E) atomicAdd(&g_cnt[edge_id(ei, (size_t)E + e)], 1);
}

// pass 1: per-block inclusive scan of PADDED counts (1024/block), dinv fused
__global__ void k_scan1(int n) {
    __shared__ int wsum[32];
    int tid = threadIdx.x, lane = tid & 31, wid = tid >> 5;
    int i = blockIdx.x * 1024 + tid;
    int v = (i < n) ? g_cnt[i] : 0;
    if (i < n) g_dinv[i] = rsqrtf((float)(v + 1));  // +1 self loop
    int x = (v + 7) & ~7;                           // pad rows to multiple of 8
    #pragma unroll
    for (int d = 1; d < 32; d <<= 1) {
        int t = __shfl_up_sync(0xffffffffu, x, d);
        if (lane >= d) x += t;
    }
    if (lane == 31) wsum[wid] = x;
    __syncthreads();
    if (wid == 0) {
        int y = wsum[lane];
        #pragma unroll
        for (int d = 1; d < 32; d <<= 1) {
            int t = __shfl_up_sync(0xffffffffu, y, d);
            if (lane >= d) y += t;
        }
        wsum[lane] = y;
    }
    __syncthreads();
    int incl = x + ((wid > 0) ? wsum[wid - 1] : 0);
    if (i < n) g_cursor[i] = incl;
    if (tid == 1023) g_bsum[blockIdx.x] = incl;
}

// pass 2: exclusive scan of <=128 block sums
__global__ void k_scan2(int nb) {
    __shared__ int ws[4];
    __shared__ int woff[4];
    int tid = threadIdx.x, lane = tid & 31, wid = tid >> 5;
    int v = (tid < nb) ? g_bsum[tid] : 0;
    int x = v;
    #pragma unroll
    for (int d = 1; d < 32; d <<= 1) {
        int t = __shfl_up_sync(0xffffffffu, x, d);
        if (lane >= d) x += t;
    }
    if (lane == 31) ws[wid] = x;
    __syncthreads();
    if (tid == 0) {
        int s = 0;
        #pragma unroll
        for (int w = 0; w < 4; w++) { woff[w] = s; s += ws[w]; }
    }
    __syncthreads();
    if (tid < nb) g_boff[tid] = x - v + woff[wid];
}

// pass 3: add block offsets -> rowoff / cursor (padded layout)
__global__ void k_scan3(int n) {
    int i = blockIdx.x * blockDim.x + threadIdx.x;
    if (i < n) {
        int incl = g_cursor[i] + g_boff[i >> 10];
        g_rowoff[i + 1] = incl;
        g_cursor[i]     = incl - ((g_cnt[i] + 7) & ~7);  // row start
    }
    if (i == 0) g_rowoff[0] = 0;
}

__global__ void k_fill(const void* __restrict__ ei, int E) {
    int e = blockIdx.x * blockDim.x + threadIdx.x;
    if (e < E) {
        int s = edge_id(ei, (size_t)e);
        int d = edge_id(ei, (size_t)E + e);
        int j = atomicAdd(&g_cursor[d], 1);
        float w = g_dinv[s] * g_dinv[d];
        g_ew[j] = ((long long)((unsigned long long)__float_as_uint(w) << 32))
                | (long long)(unsigned)s;
    }
}

// fill padding slots with (w=0, col=0)
__global__ void k_pad(int n) {
    int i = blockIdx.x * blockDim.x + threadIdx.x;
    if (i < n) {
        int e = g_rowoff[i + 1];
        for (int j = g_cursor[i]; j < e; j++) g_ew[j] = 0;
    }
}

// ---------------- dense transform: g_h16 = (X @ W) as fp16 --------------
// use_ext=1: read fp32 external x.  use_ext=0: read fp16 g_a16 (device symbol).
template <int DOUT, int R>
__global__ void k_gemm(const float* __restrict__ x_ext, int use_ext,
                       const float* __restrict__ Wg, int n) {
    constexpr int COLG = DOUT / 4;        // 4-col groups per thread
    constexpr int TY   = 256 / COLG;
    constexpr int ROWS = TY * R;          // = 64
    __shared__ __align__(16) float Ws[64 * DOUT];
    __shared__ __align__(16) float Xs[ROWS][64];

    int tid = threadIdx.x;
    for (int i = tid; i < 64 * DOUT / 4; i += 256)
        ((float4*)Ws)[i] = ((const float4*)Wg)[i];

    int row0 = blockIdx.x * ROWS;
    for (int i = tid; i < ROWS * 16; i += 256) {
        int r = i >> 4, q = i & 15;
        int row = row0 + r;
        float4 f = make_float4(0.f, 0.f, 0.f, 0.f);
        if (row < n) {
            if (use_ext) {
                f = ((const float4*)x_ext)[(size_t)row * 16 + q];
            } else {
                uint2 v = ((const uint2*)g_a16)[(size_t)row * 16 + q];
                float2 f0 = __half22float2(*(const __half2*)&v.x);
                float2 f1 = __half22float2(*(const __half2*)&v.y);
                f = make_float4(f0.x, f0.y, f1.x, f1.y);
            }
        }
        *(float4*)&Xs[r][q * 4] = f;
    }
    __syncthreads();

    int tx = tid % COLG;
    int ty = tid / COLG;
    unsigned long long a01[R], a23[R];
    #pragma unroll
    for (int r = 0; r < R; r++) { a01[r] = 0ull; a23[r] = 0ull; }

    #pragma unroll
    for (int k4 = 0; k4 < 16; k4++) {
        float4 xv[R];
        #pragma unroll
        for (int r = 0; r < R; r++)
            xv[r] = *(const float4*)&Xs[ty * R + r][k4 * 4];
        #pragma unroll
        for (int kk = 0; kk < 4; kk++) {
            ulonglong2 wv = *(const ulonglong2*)&Ws[(k4 * 4 + kk) * DOUT + tx * 4];
            #pragma unroll
            for (int r = 0; r < R; r++) {
                float xs = (kk == 0) ? xv[r].x : (kk == 1) ? xv[r].y
                         : (kk == 2) ? xv[r].z : xv[r].w;
                unsigned long long xx = pack_dup(xs);
                ffma2(a01[r], xx, wv.x);
                ffma2(a23[r], xx, wv.y);
            }
        }
    }

    uint2* __restrict__ Y = (uint2*)g_h16;
    #pragma unroll
    for (int r = 0; r < R; r++) {
        int row = row0 + ty * R + r;
        if (row < n) {
            float2 f01 = unpack2(a01[r]);
            float2 f23 = unpack2(a23[r]);
            __half2 h0 = __floats2half2_rn(f01.x, f01.y);
            __half2 h1 = __floats2half2_rn(f23.x, f23.y);
            uint2 o;
            o.x = *(unsigned*)&h0;
            o.y = *(unsigned*)&h1;
            Y[(size_t)row * COLG + tx] = o;
        }
    }
}

// unpack uint4 (8 fp16) -> 2 float4, fma by scalar w
__device__ __forceinline__ void fma8(float4& a0, float4& a1, float w, uint4 v) {
    float2 p0 = __half22float2(*(const __half2*)&v.x);
    float2 p1 = __half22float2(*(const __half2*)&v.y);
    float2 p2 = __half22float2(*(const __half2*)&v.z);
    float2 p3 = __half22float2(*(const __half2*)&v.w);
    a0.x += w * p0.x; a0.y += w * p0.y; a0.z += w * p1.x; a0.w += w * p1.y;
    a1.x += w * p2.x; a1.y += w * p2.y; a1.z += w * p3.x; a1.w += w * p3.y;
}

// ---------------- aggregation: 8 lanes/edge, 8 edges per iter -----------
// lane: eg = lane>>3 (edge-pair group 0..3), q = lane&7 (feature octet).
// Per iter: 1 LDG.128 (2 edge words) + 2 LDG.128 (H rows). Rows padded to 8.
__global__ void k_agg64(const float* __restrict__ bias, int n, int relu) {
    int warp = (blockIdx.x * blockDim.x + threadIdx.x) >> 5;
    int lane = threadIdx.x & 31;
    if (warp >= n) return;
    int eg = lane >> 3;
    int q  = lane & 7;
    int beg = g_rowoff[warp];
    int end = g_rowoff[warp + 1];
    const uint4* __restrict__ Hv = (const uint4*)g_h16;

    float4 aA0 = make_float4(0.f, 0.f, 0.f, 0.f);
    float4 aA1 = make_float4(0.f, 0.f, 0.f, 0.f);
    float4 aB0 = make_float4(0.f, 0.f, 0.f, 0.f);
    float4 aB1 = make_float4(0.f, 0.f, 0.f, 0.f);

    if (eg == 0) {  // self loop
        float di = g_dinv[warp];
        uint4 hv = Hv[(size_t)warp * 8 + q];
        fma8(aA0, aA1, di * di, hv);
    }

    for (int j = beg; j < end; j += 8) {
        ulonglong2 ee = ((const ulonglong2*)g_ew)[(j >> 1) + eg];
        unsigned cA = (unsigned)ee.x;
        unsigned cB = (unsigned)ee.y;
        float wA = __uint_as_float((unsigned)(ee.x >> 32));
        float wB = __uint_as_float((unsigned)(ee.y >> 32));
        uint4 vA = Hv[(size_t)cA * 8 + q];
        uint4 vB = Hv[(size_t)cB * 8 + q];
        fma8(aA0, aA1, wA, vA);
        fma8(aB0, aB1, wB, vB);
    }
    aA0.x += aB0.x; aA0.y += aB0.y; aA0.z += aB0.z; aA0.w += aB0.w;
    aA1.x += aB1.x; aA1.y += aB1.y; aA1.z += aB1.z; aA1.w += aB1.w;

    // reduce across the 4 edge groups (lanes q, q+8, q+16, q+24)
    #pragma unroll
    for (int d = 8; d < 32; d <<= 1) {
        aA0.x += __shfl_xor_sync(0xffffffffu, aA0.x, d);
        aA0.y += __shfl_xor_sync(0xffffffffu, aA0.y, d);
        aA0.z += __shfl_xor_sync(0xffffffffu, aA0.z, d);
        aA0.w += __shfl_xor_sync(0xffffffffu, aA0.w, d);
        aA1.x += __shfl_xor_sync(0xffffffffu, aA1.x, d);
        aA1.y += __shfl_xor_sync(0xffffffffu, aA1.y, d);
        aA1.z += __shfl_xor_sync(0xffffffffu, aA1.z, d);
        aA1.w += __shfl_xor_sync(0xffffffffu, aA1.w, d);
    }

    if (lane < 8) {
        float4 b0 = ((const float4*)bias)[q * 2];
        float4 b1 = ((const float4*)bias)[q * 2 + 1];
        aA0.x += b0.x; aA0.y += b0.y; aA0.z += b0.z; aA0.w += b0.w;
        aA1.x += b1.x; aA1.y += b1.y; aA1.z += b1.z; aA1.w += b1.w;
        if (relu) {
            aA0.x = fmaxf(aA0.x, 0.f); aA0.y = fmaxf(aA0.y, 0.f);
            aA0.z = fmaxf(aA0.z, 0.f); aA0.w = fmaxf(aA0.w, 0.f);
            aA1.x = fmaxf(aA1.x, 0.f); aA1.y = fmaxf(aA1.y, 0.f);
            aA1.z = fmaxf(aA1.z, 0.f); aA1.w = fmaxf(aA1.w, 0.f);
        }
        __half2 h0 = __floats2half2_rn(aA0.x, aA0.y);
        __half2 h1 = __floats2half2_rn(aA0.z, aA0.w);
        __half2 h2 = __floats2half2_rn(aA1.x, aA1.y);
        __half2 h3 = __floats2half2_rn(aA1.z, aA1.w);
        uint4 o;
        o.x = *(unsigned*)&h0; o.y = *(unsigned*)&h1;
        o.z = *(unsigned*)&h2; o.w = *(unsigned*)&h3;
        ((uint4*)g_a16)[(size_t)warp * 8 + q] = o;
    }
}

// D=16 final layer: 4 lanes/edge (uint2 = 4 feats), 8 edges per iter.
__global__ void k_agg16(const float* __restrict__ bias, float* __restrict__ out, int n) {
    int warp = (blockIdx.x * blockDim.x + threadIdx.x) >> 5;
    int lane = threadIdx.x & 31;
    if (warp >= n) return;
    int eg = lane >> 2;        // edge group 0..7
    int q  = lane & 3;         // feature quad 0..3
    int beg = g_rowoff[warp];
    int end = g_rowoff[warp + 1];
    const uint2* __restrict__ Hv = (const uint2*)g_h16;  // row = 16 fp16 = 4 uint2

    float4 acc = make_float4(0.f, 0.f, 0.f, 0.f);
    if (eg == 0) {  // self loop
        float di = g_dinv[warp];
        float dd = di * di;
        uint2 hv = Hv[(size_t)warp * 4 + q];
        float2 p0 = __half22float2(*(const __half2*)&hv.x);
        float2 p1 = __half22float2(*(const __half2*)&hv.y);
        acc.x = dd * p0.x; acc.y = dd * p0.y; acc.z = dd * p1.x; acc.w = dd * p1.y;
    }

    for (int j = beg; j < end; j += 8) {
        long long e = g_ew[j + eg];
        unsigned c = (unsigned)e;
        float w = __uint_as_float((unsigned)((unsigned long long)e >> 32));
        uint2 v = Hv[(size_t)c * 4 + q];
        float2 p0 = __half22float2(*(const __half2*)&v.x);
        float2 p1 = __half22float2(*(const __half2*)&v.y);
        acc.x += w * p0.x; acc.y += w * p0.y; acc.z += w * p1.x; acc.w += w * p1.y;
    }

    #pragma unroll
    for (int d = 4; d < 32; d <<= 1) {
        acc.x += __shfl_xor_sync(0xffffffffu, acc.x, d);
        acc.y += __shfl_xor_sync(0xffffffffu, acc.y, d);
        acc.z += __shfl_xor_sync(0xffffffffu, acc.z, d);
        acc.w += __shfl_xor_sync(0xffffffffu, acc.w, d);
    }

    if (lane < 4) {
        float4 b4 = ((const float4*)bias)[q];
        float4 o = make_float4(acc.x + b4.x, acc.y + b4.y,
                               acc.z + b4.z, acc.w + b4.w);
        ((float4*)out)[(size_t)warp * 4 + q] = o;
    }
}

// ---------------- launch ------------------------------------------------
extern "C" void kernel_launch(void* const* d_in, const int* in_sizes, int n_in,
                              void* d_out, int out_size) {
    const float* x  = (const float*)d_in[0];
    const void*  ei = d_in[1];
    const float* W1 = (const float*)d_in[2];  const float* b1 = (const float*)d_in[3];
    const float* W2 = (const float*)d_in[4];  const float* b2 = (const float*)d_in[5];
    const float* W3 = (const float*)d_in[6];  const float* b3 = (const float*)d_in[7];
    const float* W4 = (const float*)d_in[8];  const float* b4 = (const float*)d_in[9];
    float* out = (float*)d_out;

    int n = in_sizes[0] / 64;   // 100000
    int E = in_sizes[1] / 2;    // 1600000

    int nb_n  = (n + 255) / 256;
    int nb_e  = (E + 255) / 256;
    int nb_s1 = (n + 1023) / 1024;            // <=128
    int nb_g  = (n + 63) / 64;
    int nb_a  = ((n * 32) + 255) / 256;

    // CSR build (padded rows)
    k_init<<<nb_n, 256>>>((const int*)ei, n);
    k_count<<<nb_e, 256>>>(ei, E);
    k_scan1<<<nb_s1, 1024>>>(n);
    k_scan2<<<1, 128>>>(nb_s1);
    k_scan3<<<nb_n, 256>>>(n);
    k_fill<<<nb_e, 256>>>(ei, E);
    k_pad<<<nb_n, 256>>>(n);

    // layer 1 (fp32 input)
    k_gemm<64, 4><<<nb_g, 256>>>(x, 1, W1, n);
    k_agg64<<<nb_a, 256>>>(b1, n, 1);
    // layers 2-3 (fp16 input from g_a16, selected device-side)
    k_gemm<64, 4><<<nb_g, 256>>>(x, 0, W2, n);
    k_agg64<<<nb_a, 256>>>(b2, n, 1);
    k_gemm<64, 4><<<nb_g, 256>>>(x, 0, W3, n);
    k_agg64<<<nb_a, 256>>>(b3, n, 1);
    // layer 4 (D_OUT = 16, no relu)
    k_gemm<16, 1><<<nb_g, 256>>>(x, 0, W4, n);
    k_agg16<<<nb_a, 256>>>(b4, out, n);
}